// round 1
// baseline (speedup 1.0000x reference)
#include <cuda_runtime.h>
#include <cuda_bf16.h>
#include <cstdint>

// ---------------------------------------------------------------------------
// SpatialCrossAttention (BEVFormer-style, single level)
// b=1, n=6 cams, q=4096, d=256, HEADS=8, POINTS=8, DZ=4, Hs=56, Ws=100
// ---------------------------------------------------------------------------

#define NCAM 6
#define NQ 4096
#define D 256
#define HEADS 8
#define DH 32
#define POINTS 8
#define HS 56
#define WS 100
#define HW (HS * WS)          // 5600
#define M_VAL (NCAM * HW)     // 33600
#define M_Q   (NCAM * NQ)     // 24576

// ------------------------- scratch (device globals) ------------------------
__device__ float g_src  [M_VAL * D];      // (cam*hw, 256) features+embeds
__device__ float g_value[M_VAL * D];      // value projection
__device__ float g_qp   [M_Q * D];        // queries + pos_emb
__device__ float g_off  [M_Q * 128];      // raw offsets (pre-normalizer)
__device__ float g_attn [M_Q * 64];       // attention logits
__device__ float g_out  [M_Q * D];        // per-camera attention output
__device__ float g_slots[NQ * D];         // camera-combined, count-normalized
__device__ float g_slots2[NQ * D];        // after W_attn_out
__device__ float g_validf[M_Q];           // per (cam,q) validity 0/1
__device__ float g_invc  [NQ];            // 1/max(count,1)
__device__ float g_vscale[NQ];            // sum(valid)/max(count,1) in {0,1}
__device__ int   g_maskmode;              // 0 = byte mask, 1 = 32-bit mask

// ------------------------- build src (transpose + embeds) ------------------
// src[(cam*HW+p)*D + c] = features[cam][c][p] + lvl[c] + cam_emb[cam][c]
__global__ void k_build_src(const float* __restrict__ feat,
                            const float* __restrict__ lvl,
                            const float* __restrict__ camEmb) {
    __shared__ float tile[32][33];
    int cam = blockIdx.z;
    int p0 = blockIdx.x * 32;
    int c0 = blockIdx.y * 32;
    int tx = threadIdx.x, ty = threadIdx.y;   // 32 x 8
    const float* f = feat + (size_t)cam * D * HW;
    #pragma unroll
    for (int j = 0; j < 4; j++) {
        int c = c0 + ty + j * 8;
        int p = p0 + tx;
        tile[ty + j * 8][tx] = (p < HW) ? f[(size_t)c * HW + p] : 0.f;
    }
    __syncthreads();
    #pragma unroll
    for (int j = 0; j < 4; j++) {
        int p = p0 + ty + j * 8;
        int c = c0 + tx;
        if (p < HW)
            g_src[((size_t)cam * HW + p) * D + c] =
                tile[tx][ty + j * 8] + lvl[c] + camEmb[cam * D + c];
    }
}

// ------------------------- qp = queries + pos_emb ---------------------------
__global__ void k_build_qp(const float4* __restrict__ q4,
                           const float4* __restrict__ pe4) {
    const int per = NQ * D / 4;               // 262144
    int i = blockIdx.x * blockDim.x + threadIdx.x;
    if (i >= NCAM * per) return;
    float4 a = q4[i];
    float4 b = pe4[i % per];
    float4 r = make_float4(a.x + b.x, a.y + b.y, a.z + b.z, a.w + b.w);
    ((float4*)g_qp)[i] = r;
}

// ------------------------- SGEMM: C = A * B^T + rowscale*bias ---------------
// A: MxK row-major, B: NxK row-major (weight rows = outputs), K % 8 == 0
__global__ void __launch_bounds__(256)
k_sgemm_tn(const float* __restrict__ A, const float* __restrict__ B,
           const float* __restrict__ bias, const float* __restrict__ rowscale,
           float* __restrict__ C, int M, int N, int K) {
    __shared__ float As[8][128];
    __shared__ float Bs[8][128];
    int m0 = blockIdx.y * 128;
    int n0 = blockIdx.x * 128;
    int tid = threadIdx.x;
    int lr = tid >> 1;             // 0..127
    int lc = (tid & 1) * 4;        // 0 or 4
    int ty = tid >> 4, tx = tid & 15;
    float acc[8][8];
    #pragma unroll
    for (int i = 0; i < 8; i++)
        #pragma unroll
        for (int j = 0; j < 8; j++) acc[i][j] = 0.f;

    for (int kt = 0; kt < K; kt += 8) {
        float4 av = make_float4(0.f, 0.f, 0.f, 0.f);
        int am = m0 + lr;
        if (am < M) av = *(const float4*)(A + (size_t)am * K + kt + lc);
        As[lc + 0][lr] = av.x; As[lc + 1][lr] = av.y;
        As[lc + 2][lr] = av.z; As[lc + 3][lr] = av.w;
        float4 bv = make_float4(0.f, 0.f, 0.f, 0.f);
        int bn = n0 + lr;
        if (bn < N) bv = *(const float4*)(B + (size_t)bn * K + kt + lc);
        Bs[lc + 0][lr] = bv.x; Bs[lc + 1][lr] = bv.y;
        Bs[lc + 2][lr] = bv.z; Bs[lc + 3][lr] = bv.w;
        __syncthreads();
        #pragma unroll
        for (int k = 0; k < 8; k++) {
            float ra[8], rb[8];
            *(float4*)&ra[0] = *(const float4*)&As[k][ty * 8];
            *(float4*)&ra[4] = *(const float4*)&As[k][ty * 8 + 4];
            *(float4*)&rb[0] = *(const float4*)&Bs[k][tx * 8];
            *(float4*)&rb[4] = *(const float4*)&Bs[k][tx * 8 + 4];
            #pragma unroll
            for (int i = 0; i < 8; i++)
                #pragma unroll
                for (int j = 0; j < 8; j++)
                    acc[i][j] += ra[i] * rb[j];
        }
        __syncthreads();
    }
    #pragma unroll
    for (int i = 0; i < 8; i++) {
        int row = m0 + ty * 8 + i;
        if (row >= M) continue;
        float rs = rowscale ? rowscale[row] : 1.f;
        #pragma unroll
        for (int j = 0; j < 8; j++) {
            int col = n0 + tx * 8 + j;
            if (col < N) {
                float v = acc[i][j];
                if (bias) v += rs * bias[col];
                C[(size_t)row * N + col] = v;
            }
        }
    }
}

// ------------------------- bev_mask layout detector -------------------------
// Distinguish byte-mask (bool/uint8) from 32-bit mask (int32 or float32):
//   int32 storage:  bytes at pos%4 != 0 are all zero
//   float32 storage: bytes at pos%4 == 0 are all zero (0.0f / 1.0f)
//   uint8 storage:  both populated (Bernoulli 0.5 over >16K bytes)
__global__ void k_detect_mask(const unsigned char* __restrict__ mask) {
    __shared__ int s_lo, s_hi;
    if (threadIdx.x == 0) { s_lo = 0; s_hi = 0; }
    __syncthreads();
    int lo = 0, hi = 0;
    for (int i = threadIdx.x; i < 16384; i += blockDim.x) {
        unsigned char b = mask[i];
        if ((i & 3) == 0) lo |= b; else hi |= b;
    }
    if (lo) atomicOr(&s_lo, 1);
    if (hi) atomicOr(&s_hi, 1);
    __syncthreads();
    if (threadIdx.x == 0)
        g_maskmode = (s_lo == 0 || s_hi == 0) ? 1 : 0;  // 1 = 32-bit elements
}

// valid[cam,q] = any_z( mask[0,cam,q,z,0] )
__global__ void k_valid(const unsigned char* __restrict__ mask) {
    int i = blockIdx.x * blockDim.x + threadIdx.x;  // cam*NQ + q
    if (i >= M_Q) return;
    bool v;
    if (g_maskmode) {
        const unsigned int* m = (const unsigned int*)mask;
        v = (m[(size_t)i * 8 + 0] | m[(size_t)i * 8 + 2] |
             m[(size_t)i * 8 + 4] | m[(size_t)i * 8 + 6]) != 0u;
    } else {
        const unsigned char* m = mask + (size_t)i * 8;
        v = (m[0] | m[2] | m[4] | m[6]) != 0;
    }
    g_validf[i] = v ? 1.f : 0.f;
}

__global__ void k_count() {
    int q = blockIdx.x * blockDim.x + threadIdx.x;
    if (q >= NQ) return;
    float c = 0.f;
    #pragma unroll
    for (int cam = 0; cam < NCAM; cam++) c += g_validf[cam * NQ + q];
    float cc = fmaxf(c, 1.f);
    g_invc[q] = 1.f / cc;
    g_vscale[q] = (c > 0.f) ? 1.f : 0.f;
}

// ------------------------- softmax + bilinear sampling ----------------------
// one block per (cam*NQ + q); one warp per head; lane = dh channel
__global__ void __launch_bounds__(256)
k_sample(const float* __restrict__ ref) {
    int m = blockIdx.x;            // 0..24575
    int cam = m >> 12;
    int head = threadIdx.x >> 5;
    int lane = threadIdx.x & 31;

    const float* aL = g_attn + (size_t)m * 64 + head * 8;
    float w[POINTS];
    float mx = -1e30f;
    #pragma unroll
    for (int p = 0; p < POINTS; p++) { w[p] = aL[p]; mx = fmaxf(mx, w[p]); }
    float sum = 0.f;
    #pragma unroll
    for (int p = 0; p < POINTS; p++) { w[p] = __expf(w[p] - mx); sum += w[p]; }
    float inv = 1.f / sum;

    const float* offL = g_off + (size_t)m * 128 + head * 16;
    const float* refL = ref + (size_t)m * 8;
    const float* vbase = g_value + (size_t)cam * HW * D + head * DH + lane;

    float acc = 0.f;
    #pragma unroll
    for (int p = 0; p < POINTS; p++) {
        int z = p & 3;                               // P reshaped (2, DZ=4)
        float x = refL[z * 2 + 0] * (float)WS + offL[p * 2 + 0] - 0.5f;
        float y = refL[z * 2 + 1] * (float)HS + offL[p * 2 + 1] - 0.5f;
        float x0f = floorf(x), y0f = floorf(y);
        int x0 = (int)x0f, y0 = (int)y0f;
        float wx1 = x - x0f, wx0 = 1.f - wx1;
        float wy1 = y - y0f, wy0 = 1.f - wy1;
        float s = 0.f;
        bool xin0 = (x0 >= 0) && (x0 < WS);
        bool xin1 = (x0 + 1 >= 0) && (x0 + 1 < WS);
        if (y0 >= 0 && y0 < HS) {
            if (xin0) s += wx0 * wy0 * vbase[(size_t)(y0 * WS + x0) * D];
            if (xin1) s += wx1 * wy0 * vbase[(size_t)(y0 * WS + x0 + 1) * D];
        }
        if (y0 + 1 >= 0 && y0 + 1 < HS) {
            if (xin0) s += wx0 * wy1 * vbase[(size_t)((y0 + 1) * WS + x0) * D];
            if (xin1) s += wx1 * wy1 * vbase[(size_t)((y0 + 1) * WS + x0 + 1) * D];
        }
        acc += (w[p] * inv) * s;
    }
    g_out[(size_t)m * D + head * DH + lane] = acc;
}

// ------------------------- camera combine -----------------------------------
__global__ void k_combine() {
    int i = blockIdx.x * blockDim.x + threadIdx.x;  // q*D + c
    if (i >= NQ * D) return;
    int q = i >> 8;
    float s = 0.f;
    #pragma unroll
    for (int cam = 0; cam < NCAM; cam++)
        s += g_validf[cam * NQ + q] * g_out[(size_t)cam * NQ * D + i];
    g_slots[i] = s * g_invc[q];
}

// ---------------------------------------------------------------------------
extern "C" void kernel_launch(void* const* d_in, const int* in_sizes, int n_in,
                              void* d_out, int out_size) {
    const float* queries   = (const float*)d_in[0];
    const float* pos_emb   = (const float*)d_in[1];
    const float* lvl_emb   = (const float*)d_in[2];
    const float* cam_emb   = (const float*)d_in[3];
    const float* features  = (const float*)d_in[4];
    const float* ref_pts   = (const float*)d_in[5];
    const float* W_off     = (const float*)d_in[6];
    const float* b_off     = (const float*)d_in[7];
    const float* W_attn    = (const float*)d_in[8];
    const float* b_attn    = (const float*)d_in[9];
    const float* W_val     = (const float*)d_in[10];
    const float* b_val     = (const float*)d_in[11];
    const float* W_ao      = (const float*)d_in[12];
    const float* b_ao      = (const float*)d_in[13];
    const float* W_out     = (const float*)d_in[14];
    const float* b_out     = (const float*)d_in[15];
    const unsigned char* bev_mask = (const unsigned char*)d_in[16];
    float* out = (float*)d_out;

    float *p_src, *p_value, *p_qp, *p_off, *p_attn, *p_slots, *p_slots2, *p_vscale;
    cudaGetSymbolAddress((void**)&p_src,    g_src);
    cudaGetSymbolAddress((void**)&p_value,  g_value);
    cudaGetSymbolAddress((void**)&p_qp,     g_qp);
    cudaGetSymbolAddress((void**)&p_off,    g_off);
    cudaGetSymbolAddress((void**)&p_attn,   g_attn);
    cudaGetSymbolAddress((void**)&p_slots,  g_slots);
    cudaGetSymbolAddress((void**)&p_slots2, g_slots2);
    cudaGetSymbolAddress((void**)&p_vscale, g_vscale);

    // 1. src = transpose(features) + level + camera embeddings
    k_build_src<<<dim3((HW + 31) / 32, D / 32, NCAM), dim3(32, 8)>>>(
        features, lvl_emb, cam_emb);

    // 2. qp = queries + pos_emb
    {
        int n4 = NCAM * NQ * D / 4;
        k_build_qp<<<(n4 + 255) / 256, 256>>>((const float4*)queries,
                                              (const float4*)pos_emb);
    }

    // 3. value = src @ W_val^T + b_val        (33600 x 256 x 256)
    k_sgemm_tn<<<dim3(2, (M_VAL + 127) / 128), 256>>>(
        p_src, W_val, b_val, nullptr, p_value, M_VAL, D, D);

    // 4. off = qp @ W_off^T + b_off           (24576 x 128 x 256)
    k_sgemm_tn<<<dim3(1, M_Q / 128), 256>>>(
        p_qp, W_off, b_off, nullptr, p_off, M_Q, 128, D);

    // 5. attn logits = qp @ W_attn^T + b_attn (24576 x 64 x 256)
    k_sgemm_tn<<<dim3(1, M_Q / 128), 256>>>(
        p_qp, W_attn, b_attn, nullptr, p_attn, M_Q, 64, D);

    // 6. mask validity
    k_detect_mask<<<1, 256>>>(bev_mask);
    k_valid<<<(M_Q + 255) / 256, 256>>>(bev_mask);
    k_count<<<(NQ + 255) / 256, 256>>>();

    // 7. softmax + bilinear sampling + weighted sum -> g_out
    k_sample<<<M_Q, 256>>>(ref_pts);

    // 8. camera masked-sum + count normalization -> g_slots (4096 x 256)
    k_combine<<<(NQ * D + 255) / 256, 256>>>();

    // 9. slots2 = slots @ W_attn_out^T + vscale*b_attn_out (4096 x 256 x 256)
    k_sgemm_tn<<<dim3(2, NQ / 128), 256>>>(
        p_slots, W_ao, b_ao, p_vscale, p_slots2, NQ, D, D);

    // 10. out = slots2 @ W_out^T + b_out      (4096 x 256 x 256)
    k_sgemm_tn<<<dim3(2, NQ / 128), 256>>>(
        p_slots2, W_out, b_out, nullptr, out, NQ, D, D);
}